// round 13
// baseline (speedup 1.0000x reference)
#include <cuda_runtime.h>
#include <math.h>
#include <stdint.h>

// Problem constants (fixed by the dataset)
#define NN 100000   // nodes
#define EE 800000   // edges
#define F0 58       // input features
#define H1 300
#define H2 100

// -------- persistent device scratch (allocation-free rule: __device__ globals) ----
__device__ int   g_is64;
__device__ float g_deg[NN];                  // out-degree -> dinv (in place)
__device__ int   g_cnt[NN];                  // in-degree (CSR counts by dst)
__device__ int   g_ptr[NN + 1];              // CSR row pointers (by dst)
__device__ int   g_fill[NN];                 // CSR fill cursors
__device__ int   g_part[512];                // per-block count sums
__device__ int   g_pref[512];                // exclusive prefix of g_part
__device__ int   g_src32[EE];
__device__ int   g_dst32[EE];
__device__ int   g_csr_src[EE];              // src per dst-sorted edge
__device__ float g_csr_w[EE];                // weight per dst-sorted edge
__device__ float g_tx1[(size_t)NN * 64];     // layer1 gather result, ld=64
__device__ float g_h1[(size_t)NN * H1];      // relu(layer1)
__device__ float g_yz2[(size_t)NN * 2 * H2]; // [y2+b2 | z2], ld=200
__device__ float g_z3[NN];
__device__ float g_out[NN];

#define NBLK 391   // ceil(NN/256)

// ============================ edge-index intake ==================================
__global__ void k_detect(const int* __restrict__ ei32) {
    int t = threadIdx.x;
    unsigned bad = __ballot_sync(0xffffffffu, ei32[2 * t + 1] != 0);
    if (t == 0) g_is64 = (bad == 0u) ? 1 : 0;
}

__global__ void k_init() {
    int i = blockIdx.x * blockDim.x + threadIdx.x;
    if (i < NN) { g_deg[i] = 0.f; g_cnt[i] = 0; }
}

// compact + degree/count atomics in one pass
__global__ void k_compact(const int* __restrict__ ei32) {
    int e = blockIdx.x * blockDim.x + threadIdx.x;
    if (e >= EE) return;
    int s, d;
    if (g_is64) {
        s = ei32[2 * e];
        d = ei32[2 * EE + 2 * e];
    } else {
        s = ei32[e];
        d = ei32[EE + e];
    }
    g_src32[e] = s;
    g_dst32[e] = d;
    atomicAdd(&g_deg[s], 1.0f);
    atomicAdd(&g_cnt[d], 1);
}

// ============================ parallel scan (dinv folded into k_part) ============
__global__ void __launch_bounds__(256) k_part() {
    __shared__ int sh[256];
    int t = threadIdx.x;
    int i = blockIdx.x * 256 + t;
    if (i < NN) {                       // dinv transform (g_deg complete here)
        float d = g_deg[i];
        g_deg[i] = (d > 0.f) ? rsqrtf(d) : 0.f;
    }
    sh[t] = (i < NN) ? g_cnt[i] : 0;
    __syncthreads();
    for (int off = 128; off > 0; off >>= 1) {
        if (t < off) sh[t] += sh[t + off];
        __syncthreads();
    }
    if (t == 0) g_part[blockIdx.x] = sh[0];
}

__global__ void __launch_bounds__(512) k_spart() {
    __shared__ int a[512], b[512];
    int t = threadIdx.x;
    int v = (t < NBLK) ? g_part[t] : 0;
    int orig = v;
    a[t] = v;
    __syncthreads();
    int* cur = a; int* nxt = b;
    for (int off = 1; off < 512; off <<= 1) {
        int x = cur[t];
        if (t >= off) x += cur[t - off];
        nxt[t] = x;
        __syncthreads();
        int* tmp = cur; cur = nxt; nxt = tmp;
    }
    if (t < NBLK) g_pref[t] = cur[t] - orig;   // exclusive
    if (t == 0) g_ptr[NN] = EE;
}

__global__ void __launch_bounds__(256) k_apply() {
    __shared__ int a[256], b[256];
    int t = threadIdx.x;
    int i = blockIdx.x * 256 + t;
    int v = (i < NN) ? g_cnt[i] : 0;
    int orig = v;
    a[t] = v;
    __syncthreads();
    int* cur = a; int* nxt = b;
    for (int off = 1; off < 256; off <<= 1) {
        int x = cur[t];
        if (t >= off) x += cur[t - off];
        nxt[t] = x;
        __syncthreads();
        int* tmp = cur; cur = nxt; nxt = tmp;
    }
    if (i < NN) {
        int excl = cur[t] - orig + g_pref[blockIdx.x];
        g_ptr[i] = excl;
        g_fill[i] = excl;
    }
}

__global__ void k_fill() {
    int e = blockIdx.x * blockDim.x + threadIdx.x;
    if (e >= EE) return;
    int s = g_src32[e], d = g_dst32[e];
    float w = -(g_deg[s] * g_deg[d]);
    int pos = atomicAdd(&g_fill[d], 1);
    g_csr_src[pos] = s;
    g_csr_w[pos] = w;
}

// ============================ gathers (atomic-free) ==============================
__global__ void g_gather1(const float* __restrict__ x) {
    int warp = (blockIdx.x * blockDim.x + threadIdx.x) >> 5;
    int lane = threadIdx.x & 31;
    if (warp >= NN) return;
    int beg = g_ptr[warp], end = g_ptr[warp + 1];
    float ax = 0.f, ay = 0.f;
    for (int e = beg; e < end; e++) {
        int s = g_csr_src[e];
        float w = g_csr_w[e];
        if (lane < 29) {
            float2 xv = *(const float2*)(x + (long)s * F0 + lane * 2);
            ax += w * xv.x;
            ay += w * xv.y;
        }
    }
    if (lane < 29) {
        float2 o; o.x = ax; o.y = ay;
        *(float2*)(g_tx1 + (long)warp * 64 + lane * 2) = o;
    }
}

// fused: gather z2 -> +y2 -> relu -> dot with W3[0],W3[1] -> g_out, g_z3
__global__ void g_fuse2(const float* __restrict__ W3, const float* __restrict__ b3) {
    int warp = (blockIdx.x * blockDim.x + threadIdx.x) >> 5;
    int lane = threadIdx.x & 31;
    if (warp >= NN) return;
    int beg = g_ptr[warp], end = g_ptr[warp + 1];
    float4 acc; acc.x = acc.y = acc.z = acc.w = 0.f;
    for (int e = beg; e < end; e++) {
        int s = g_csr_src[e];
        float w = g_csr_w[e];
        if (lane < 25) {
            const float4 z = *(const float4*)(g_yz2 + (long)s * 200 + 100 + lane * 4);
            acc.x += w * z.x; acc.y += w * z.y; acc.z += w * z.z; acc.w += w * z.w;
        }
    }
    float s0 = 0.f, s1 = 0.f;
    if (lane < 25) {
        const float4 y = *(const float4*)(g_yz2 + (long)warp * 200 + lane * 4);
        float h0 = fmaxf(y.x + acc.x, 0.f);
        float h1 = fmaxf(y.y + acc.y, 0.f);
        float h2 = fmaxf(y.z + acc.z, 0.f);
        float h3 = fmaxf(y.w + acc.w, 0.f);
        int k = lane * 4;
        s0 = h0 * W3[k] + h1 * W3[k + 1] + h2 * W3[k + 2] + h3 * W3[k + 3];
        s1 = h0 * W3[H2 + k] + h1 * W3[H2 + k + 1] + h2 * W3[H2 + k + 2] + h3 * W3[H2 + k + 3];
    }
#pragma unroll
    for (int o = 16; o > 0; o >>= 1) {
        s0 += __shfl_down_sync(0xffffffffu, s0, o);
        s1 += __shfl_down_sync(0xffffffffu, s1, o);
    }
    if (lane == 0) {
        g_out[warp] = s0 + b3[0];
        g_z3[warp] = s1;
    }
}

// final: out[d] = g_out[d] + sum_e w_e * z3[src_e]
__global__ void g_gather3(float* __restrict__ out) {
    int d = blockIdx.x * blockDim.x + threadIdx.x;
    if (d >= NN) return;
    int beg = g_ptr[d], end = g_ptr[d + 1];
    float acc = 0.f;
    for (int e = beg; e < end; e++)
        acc += g_csr_w[e] * g_z3[g_csr_src[e]];
    out[d] = g_out[d] + acc;
}

// ============================ tf32 mma.sync GEMM (BM=128, BN=128, pipelined) =====
// 3-term split: D += Ahi*Bhi + Ahi*Blo + Alo*Bhi  (residual ~2^-22)
__device__ __forceinline__ uint32_t f2tf32(float v) {
    uint32_t r;
    asm("cvt.rna.tf32.f32 %0, %1;" : "=r"(r) : "f"(v));
    return r;
}

__device__ __forceinline__ void mma8(float* c,
                                     uint32_t a0, uint32_t a1, uint32_t a2, uint32_t a3,
                                     uint32_t b0, uint32_t b1) {
    asm volatile(
        "mma.sync.aligned.m16n8k8.row.col.f32.tf32.tf32.f32 "
        "{%0,%1,%2,%3}, {%4,%5,%6,%7}, {%8,%9}, {%0,%1,%2,%3};"
        : "+f"(c[0]), "+f"(c[1]), "+f"(c[2]), "+f"(c[3])
        : "r"(a0), "r"(a1), "r"(a2), "r"(a3), "r"(b0), "r"(b1));
}

#define SSTR 20   // padded smem k-stride -> conflict-free fragment loads

// WHICH=1: g_h1 = relu([x|g_tx1](K=116) @ W1cat + b1), NCOLS=300
// WHICH=2: g_yz2 = g_h1(K=300) @ [W2[0]|W2[1]] (+b2 on cols<100), NCOLS=200
template <int WHICH>
__global__ void __launch_bounds__(256) mma_gemm(const float* __restrict__ Asrc,
                                                const float* __restrict__ W,
                                                const float* __restrict__ bias) {
    constexpr int KTOT  = (WHICH == 1) ? (2 * F0) : H1;   // 116 / 300
    constexpr int NCOLS = (WHICH == 1) ? H1 : (2 * H2);   // 300 / 200
    constexpr int NCH   = (KTOT + 15) / 16;               // 8 / 19

    __shared__ __align__(16) uint32_t As_hi[128 * SSTR], As_lo[128 * SSTR];
    __shared__ __align__(16) uint32_t Bs_hi[128 * SSTR], Bs_lo[128 * SSTR];

    const int m0 = blockIdx.y * 128;
    const int n0 = blockIdx.x * 128;
    int tid = threadIdx.x, wid = tid >> 5, lane = tid & 31;
    int wm = wid & 3, wn = wid >> 2;        // warp: rows wm*32..+31, cols wn*64..+63
    int qm = lane >> 2, qk = lane & 3;

    float c[2][8][4];
#pragma unroll
    for (int mt = 0; mt < 2; mt++)
#pragma unroll
        for (int nt = 0; nt < 8; nt++)
#pragma unroll
            for (int i = 0; i < 4; i++) c[mt][nt][i] = 0.f;

    // prefetch registers
    float2 a2[4];
    float4 a4[2];
    float  br[8];

    auto LDG = [&](int k0) {
        if (WHICH == 1) {
#pragma unroll
            for (int j = 0; j < 4; j++) {
                int idx = tid + j * 256;              // [0,1024)
                int m = idx >> 3, kk = (idx & 7) * 2;
                int gm = m0 + m, gk = k0 + kk;
                float2 v; v.x = 0.f; v.y = 0.f;
                if (gm < NN && gk < KTOT) {
                    v = (gk < F0) ? *(const float2*)(Asrc + (long)gm * F0 + gk)
                                  : *(const float2*)(g_tx1 + (long)gm * 64 + (gk - F0));
                }
                a2[j] = v;
            }
        } else {
#pragma unroll
            for (int j = 0; j < 2; j++) {
                int idx = tid + j * 256;              // [0,512)
                int m = idx >> 2, kk = (idx & 3) * 4;
                int gm = m0 + m, gk = k0 + kk;
                float4 v; v.x = v.y = v.z = v.w = 0.f;
                if (gm < NN && gk < KTOT)
                    v = *(const float4*)(g_h1 + (long)gm * H1 + gk);
                a4[j] = v;
            }
        }
#pragma unroll
        for (int j = 0; j < 8; j++) {
            int idx = tid + j * 256;                  // [0,2048)
            int n = idx & 127, kk = idx >> 7;
            int gn = n0 + n, gk = k0 + kk;
            float v = 0.f;
            if (gk < KTOT) {
                if (WHICH == 1) {
                    if (gn < 300)
                        v = (gk < F0) ? W[(long)gk * H1 + gn]
                                      : W[(long)F0 * H1 + (long)(gk - F0) * H1 + gn];
                } else {
                    if (gn < 100) v = W[(long)gk * H2 + gn];
                    else if (gn < 200) v = W[(long)H1 * H2 + (long)gk * H2 + (gn - 100)];
                }
            }
            br[j] = v;
        }
    };

    auto STS = [&]() {
        if (WHICH == 1) {
#pragma unroll
            for (int j = 0; j < 4; j++) {
                int idx = tid + j * 256;
                int m = idx >> 3, kk = (idx & 7) * 2;
                float2 v = a2[j];
                uint32_t hx = f2tf32(v.x), hy = f2tf32(v.y);
                As_hi[m * SSTR + kk]     = hx;
                As_hi[m * SSTR + kk + 1] = hy;
                As_lo[m * SSTR + kk]     = f2tf32(v.x - __uint_as_float(hx));
                As_lo[m * SSTR + kk + 1] = f2tf32(v.y - __uint_as_float(hy));
            }
        } else {
#pragma unroll
            for (int j = 0; j < 2; j++) {
                int idx = tid + j * 256;
                int m = idx >> 2, kk = (idx & 3) * 4;
                float4 v = a4[j];
                uint32_t h0 = f2tf32(v.x), h1 = f2tf32(v.y), h2 = f2tf32(v.z), h3 = f2tf32(v.w);
                *(uint4*)&As_hi[m * SSTR + kk] = make_uint4(h0, h1, h2, h3);
                *(uint4*)&As_lo[m * SSTR + kk] = make_uint4(
                    f2tf32(v.x - __uint_as_float(h0)), f2tf32(v.y - __uint_as_float(h1)),
                    f2tf32(v.z - __uint_as_float(h2)), f2tf32(v.w - __uint_as_float(h3)));
            }
        }
#pragma unroll
        for (int j = 0; j < 8; j++) {
            int idx = tid + j * 256;
            int n = idx & 127, kk = idx >> 7;
            uint32_t h = f2tf32(br[j]);
            Bs_hi[n * SSTR + kk] = h;
            Bs_lo[n * SSTR + kk] = f2tf32(br[j] - __uint_as_float(h));
        }
    };

    LDG(0);
    for (int ch = 0; ch < NCH; ch++) {
        STS();
        __syncthreads();
        if (ch + 1 < NCH) LDG((ch + 1) * 16);   // hide gmem latency under mma mainloop

#pragma unroll
        for (int ks = 0; ks < 16; ks += 8) {
            uint32_t ah[2][4], al[2][4];
#pragma unroll
            for (int mt = 0; mt < 2; mt++) {
                int mb = wm * 32 + mt * 16;
                int r0 = (mb + qm) * SSTR + ks + qk;
                int r1 = (mb + qm + 8) * SSTR + ks + qk;
                ah[mt][0] = As_hi[r0];     ah[mt][1] = As_hi[r1];
                ah[mt][2] = As_hi[r0 + 4]; ah[mt][3] = As_hi[r1 + 4];
                al[mt][0] = As_lo[r0];     al[mt][1] = As_lo[r1];
                al[mt][2] = As_lo[r0 + 4]; al[mt][3] = As_lo[r1 + 4];
            }
#pragma unroll
            for (int nt = 0; nt < 8; nt++) {
                int nb = (wn * 64 + nt * 8 + qm) * SSTR + ks + qk;
                uint32_t bh0 = Bs_hi[nb], bh1 = Bs_hi[nb + 4];
                uint32_t bl0 = Bs_lo[nb], bl1 = Bs_lo[nb + 4];
#pragma unroll
                for (int mt = 0; mt < 2; mt++) {
                    mma8(c[mt][nt], ah[mt][0], ah[mt][1], ah[mt][2], ah[mt][3], bh0, bh1);
                    mma8(c[mt][nt], ah[mt][0], ah[mt][1], ah[mt][2], ah[mt][3], bl0, bl1);
                    mma8(c[mt][nt], al[mt][0], al[mt][1], al[mt][2], al[mt][3], bh0, bh1);
                }
            }
        }
        __syncthreads();
    }

    // ---- epilogue ----
#pragma unroll
    for (int mt = 0; mt < 2; mt++) {
#pragma unroll
        for (int nt = 0; nt < 8; nt++) {
            int r0 = m0 + wm * 32 + mt * 16 + qm;
            int col = n0 + wn * 64 + nt * 8 + 2 * qk;
#pragma unroll
            for (int half = 0; half < 2; half++) {
                int r = r0 + half * 8;
                if (r >= NN) continue;
#pragma unroll
                for (int j = 0; j < 2; j++) {
                    int cc = col + j;
                    if (cc >= NCOLS) continue;
                    float v = c[mt][nt][half * 2 + j];
                    if (WHICH == 1) {
                        v = fmaxf(v + bias[cc], 0.f);
                        g_h1[(long)r * H1 + cc] = v;
                    } else {
                        if (cc < 100) v += bias[cc];
                        g_yz2[(long)r * 200 + cc] = v;
                    }
                }
            }
        }
    }
}

// ============================ launch =============================================
extern "C" void kernel_launch(void* const* d_in, const int* in_sizes, int n_in,
                              void* d_out, int out_size) {
    const float* x    = (const float*)d_in[0];
    const int*   ei32 = (const int*)d_in[1];
    const float* W1 = (const float*)d_in[2];
    const float* b1 = (const float*)d_in[3];
    const float* W2 = (const float*)d_in[4];
    const float* b2 = (const float*)d_in[5];
    const float* W3 = (const float*)d_in[6];
    const float* b3 = (const float*)d_in[7];
    float* out = (float*)d_out;

    const int T = 256;
    const int WARP_GRID = (NN * 32 + T - 1) / T;

    k_detect<<<1, 32>>>(ei32);
    k_init<<<NBLK, T>>>();
    k_compact<<<(EE + T - 1) / T, T>>>(ei32);
    k_part<<<NBLK, T>>>();
    k_spart<<<1, 512>>>();
    k_apply<<<NBLK, T>>>();
    k_fill<<<(EE + T - 1) / T, T>>>();

    g_gather1<<<WARP_GRID, T>>>(x);
    mma_gemm<1><<<dim3(3, (NN + 127) / 128), T>>>(x, W1, b1);
    mma_gemm<2><<<dim3(2, (NN + 127) / 128), T>>>(nullptr, W2, b2);
    g_fuse2<<<WARP_GRID, T>>>(W3, b3);
    g_gather3<<<NBLK, T>>>(out);
}

// round 15
// speedup vs baseline: 1.1962x; 1.1962x over previous
#include <cuda_runtime.h>
#include <math.h>
#include <stdint.h>

// Problem constants (fixed by the dataset)
#define NN 100000   // nodes
#define EE 800000   // edges
#define F0 58       // input features
#define H1 300
#define H2 100

// -------- persistent device scratch (allocation-free rule: __device__ globals) ----
__device__ int   g_is64;
__device__ float g_deg[NN];                  // out-degree -> dinv (in place)
__device__ int   g_cnt[NN];                  // in-degree (CSR counts by dst)
__device__ int   g_ptr[NN + 1];              // CSR row pointers (by dst)
__device__ int   g_fill[NN];                 // CSR fill cursors
__device__ int   g_part[512];                // per-block count sums
__device__ int   g_pref[512];                // exclusive prefix of g_part
__device__ int   g_src32[EE];
__device__ int   g_dst32[EE];
__device__ int   g_csr_src[EE];              // src per dst-sorted edge
__device__ float g_csr_w[EE];                // weight per dst-sorted edge
__device__ float g_tx1[(size_t)NN * 64];     // layer1 gather result, ld=64
__device__ float g_h1[(size_t)NN * H1];      // relu(layer1)
__device__ float g_yz2[(size_t)NN * 2 * H2]; // [y2+b2 | z2], ld=200
__device__ float g_z3[NN];
__device__ float g_out[NN];

#define NBLK 391   // ceil(NN/256)

// ============================ edge-index intake ==================================
__global__ void k_detect(const int* __restrict__ ei32) {
    int t = threadIdx.x;
    unsigned bad = __ballot_sync(0xffffffffu, ei32[2 * t + 1] != 0);
    if (t == 0) g_is64 = (bad == 0u) ? 1 : 0;
}

__global__ void k_init() {
    int i = blockIdx.x * blockDim.x + threadIdx.x;
    if (i < NN) { g_deg[i] = 0.f; g_cnt[i] = 0; }
}

// compact + degree/count atomics in one pass
__global__ void k_compact(const int* __restrict__ ei32) {
    int e = blockIdx.x * blockDim.x + threadIdx.x;
    if (e >= EE) return;
    int s, d;
    if (g_is64) {
        // int64 layout: 8B-aligned (lo, hi) pairs -> single int2 load each
        int2 sv = *(const int2*)(ei32 + 2 * e);
        int2 dv = *(const int2*)(ei32 + 2 * EE + 2 * e);
        s = sv.x;
        d = dv.x;
    } else {
        s = ei32[e];
        d = ei32[EE + e];
    }
    g_src32[e] = s;
    g_dst32[e] = d;
    atomicAdd(&g_deg[s], 1.0f);
    atomicAdd(&g_cnt[d], 1);
}

// ============================ parallel scan (dinv folded into k_part) ============
__global__ void __launch_bounds__(256) k_part() {
    __shared__ int sh[256];
    int t = threadIdx.x;
    int i = blockIdx.x * 256 + t;
    if (i < NN) {                       // dinv transform (g_deg complete here)
        float d = g_deg[i];
        g_deg[i] = (d > 0.f) ? rsqrtf(d) : 0.f;
    }
    sh[t] = (i < NN) ? g_cnt[i] : 0;
    __syncthreads();
    for (int off = 128; off > 0; off >>= 1) {
        if (t < off) sh[t] += sh[t + off];
        __syncthreads();
    }
    if (t == 0) g_part[blockIdx.x] = sh[0];
}

__global__ void __launch_bounds__(512) k_spart() {
    __shared__ int a[512], b[512];
    int t = threadIdx.x;
    int v = (t < NBLK) ? g_part[t] : 0;
    int orig = v;
    a[t] = v;
    __syncthreads();
    int* cur = a; int* nxt = b;
    for (int off = 1; off < 512; off <<= 1) {
        int x = cur[t];
        if (t >= off) x += cur[t - off];
        nxt[t] = x;
        __syncthreads();
        int* tmp = cur; cur = nxt; nxt = tmp;
    }
    if (t < NBLK) g_pref[t] = cur[t] - orig;   // exclusive
    if (t == 0) g_ptr[NN] = EE;
}

__global__ void __launch_bounds__(256) k_apply() {
    __shared__ int a[256], b[256];
    int t = threadIdx.x;
    int i = blockIdx.x * 256 + t;
    int v = (i < NN) ? g_cnt[i] : 0;
    int orig = v;
    a[t] = v;
    __syncthreads();
    int* cur = a; int* nxt = b;
    for (int off = 1; off < 256; off <<= 1) {
        int x = cur[t];
        if (t >= off) x += cur[t - off];
        nxt[t] = x;
        __syncthreads();
        int* tmp = cur; cur = nxt; nxt = tmp;
    }
    if (i < NN) {
        int excl = cur[t] - orig + g_pref[blockIdx.x];
        g_ptr[i] = excl;
        g_fill[i] = excl;
    }
}

__global__ void k_fill() {
    int e = blockIdx.x * blockDim.x + threadIdx.x;
    if (e >= EE) return;
    int s = g_src32[e], d = g_dst32[e];
    float w = -(g_deg[s] * g_deg[d]);
    int pos = atomicAdd(&g_fill[d], 1);
    g_csr_src[pos] = s;
    g_csr_w[pos] = w;
}

// ============================ gathers (atomic-free) ==============================
__global__ void g_gather1(const float* __restrict__ x) {
    int warp = (blockIdx.x * blockDim.x + threadIdx.x) >> 5;
    int lane = threadIdx.x & 31;
    if (warp >= NN) return;
    int beg = g_ptr[warp], end = g_ptr[warp + 1];
    float ax = 0.f, ay = 0.f;
    for (int e = beg; e < end; e++) {
        int s = g_csr_src[e];
        float w = g_csr_w[e];
        if (lane < 29) {
            float2 xv = *(const float2*)(x + (long)s * F0 + lane * 2);
            ax += w * xv.x;
            ay += w * xv.y;
        }
    }
    if (lane < 29) {
        float2 o; o.x = ax; o.y = ay;
        *(float2*)(g_tx1 + (long)warp * 64 + lane * 2) = o;
    }
}

// fused: gather z2 -> +y2 -> relu -> dot with W3[0],W3[1] -> g_out, g_z3
__global__ void g_fuse2(const float* __restrict__ W3, const float* __restrict__ b3) {
    int warp = (blockIdx.x * blockDim.x + threadIdx.x) >> 5;
    int lane = threadIdx.x & 31;
    if (warp >= NN) return;
    int beg = g_ptr[warp], end = g_ptr[warp + 1];
    float4 acc; acc.x = acc.y = acc.z = acc.w = 0.f;
    for (int e = beg; e < end; e++) {
        int s = g_csr_src[e];
        float w = g_csr_w[e];
        if (lane < 25) {
            const float4 z = *(const float4*)(g_yz2 + (long)s * 200 + 100 + lane * 4);
            acc.x += w * z.x; acc.y += w * z.y; acc.z += w * z.z; acc.w += w * z.w;
        }
    }
    float s0 = 0.f, s1 = 0.f;
    if (lane < 25) {
        const float4 y = *(const float4*)(g_yz2 + (long)warp * 200 + lane * 4);
        float h0 = fmaxf(y.x + acc.x, 0.f);
        float h1 = fmaxf(y.y + acc.y, 0.f);
        float h2 = fmaxf(y.z + acc.z, 0.f);
        float h3 = fmaxf(y.w + acc.w, 0.f);
        int k = lane * 4;
        s0 = h0 * W3[k] + h1 * W3[k + 1] + h2 * W3[k + 2] + h3 * W3[k + 3];
        s1 = h0 * W3[H2 + k] + h1 * W3[H2 + k + 1] + h2 * W3[H2 + k + 2] + h3 * W3[H2 + k + 3];
    }
#pragma unroll
    for (int o = 16; o > 0; o >>= 1) {
        s0 += __shfl_down_sync(0xffffffffu, s0, o);
        s1 += __shfl_down_sync(0xffffffffu, s1, o);
    }
    if (lane == 0) {
        g_out[warp] = s0 + b3[0];
        g_z3[warp] = s1;
    }
}

// final: out[d] = g_out[d] + sum_e w_e * z3[src_e]
__global__ void g_gather3(float* __restrict__ out) {
    int d = blockIdx.x * blockDim.x + threadIdx.x;
    if (d >= NN) return;
    int beg = g_ptr[d], end = g_ptr[d + 1];
    float acc = 0.f;
    for (int e = beg; e < end; e++)
        acc += g_csr_w[e] * g_z3[g_csr_src[e]];
    out[d] = g_out[d] + acc;
}

// ============================ tf32 mma.sync GEMM (BM=128, BN=64, pipelined) ======
// 3-term split: D += Ahi*Bhi + Ahi*Blo + Alo*Bhi  (residual ~2^-22)
__device__ __forceinline__ uint32_t f2tf32(float v) {
    uint32_t r;
    asm("cvt.rna.tf32.f32 %0, %1;" : "=r"(r) : "f"(v));
    return r;
}

__device__ __forceinline__ void mma8(float* c,
                                     uint32_t a0, uint32_t a1, uint32_t a2, uint32_t a3,
                                     uint32_t b0, uint32_t b1) {
    asm volatile(
        "mma.sync.aligned.m16n8k8.row.col.f32.tf32.tf32.f32 "
        "{%0,%1,%2,%3}, {%4,%5,%6,%7}, {%8,%9}, {%0,%1,%2,%3};"
        : "+f"(c[0]), "+f"(c[1]), "+f"(c[2]), "+f"(c[3])
        : "r"(a0), "r"(a1), "r"(a2), "r"(a3), "r"(b0), "r"(b1));
}

#define SSTR 20   // padded smem k-stride -> conflict-free fragment loads

// WHICH=1: g_h1 = relu([x|g_tx1](K=116) @ W1cat + b1), NCOLS=300
// WHICH=2: g_yz2 = g_h1(K=300) @ [W2[0]|W2[1]] (+b2 on cols<100), NCOLS=200
template <int WHICH>
__global__ void __launch_bounds__(256) mma_gemm(const float* __restrict__ Asrc,
                                                const float* __restrict__ W,
                                                const float* __restrict__ bias) {
    constexpr int KTOT  = (WHICH == 1) ? (2 * F0) : H1;   // 116 / 300
    constexpr int NCOLS = (WHICH == 1) ? H1 : (2 * H2);   // 300 / 200
    constexpr int NCH   = (KTOT + 15) / 16;               // 8 / 19

    __shared__ __align__(16) uint32_t As_hi[128 * SSTR], As_lo[128 * SSTR];
    __shared__ __align__(16) uint32_t Bs_hi[64 * SSTR],  Bs_lo[64 * SSTR];

    const int m0 = blockIdx.y * 128;
    const int n0 = blockIdx.x * 64;
    int tid = threadIdx.x, wid = tid >> 5, lane = tid & 31;
    int wm = wid & 3, wn = wid >> 2;
    int qm = lane >> 2, qk = lane & 3;

    float c[2][4][4];
#pragma unroll
    for (int mt = 0; mt < 2; mt++)
#pragma unroll
        for (int nt = 0; nt < 4; nt++)
#pragma unroll
            for (int i = 0; i < 4; i++) c[mt][nt][i] = 0.f;

    // prefetch registers
    float2 a2[4];
    float4 a4[2];
    float  br[4];

    auto LDG = [&](int k0) {
        if (WHICH == 1) {
#pragma unroll
            for (int j = 0; j < 4; j++) {
                int idx = tid + j * 256;              // [0,1024)
                int m = idx >> 3, kk = (idx & 7) * 2;
                int gm = m0 + m, gk = k0 + kk;
                float2 v; v.x = 0.f; v.y = 0.f;
                if (gm < NN && gk < KTOT) {
                    v = (gk < F0) ? *(const float2*)(Asrc + (long)gm * F0 + gk)
                                  : *(const float2*)(g_tx1 + (long)gm * 64 + (gk - F0));
                }
                a2[j] = v;
            }
        } else {
#pragma unroll
            for (int j = 0; j < 2; j++) {
                int idx = tid + j * 256;              // [0,512)
                int m = idx >> 2, kk = (idx & 3) * 4;
                int gm = m0 + m, gk = k0 + kk;
                float4 v; v.x = v.y = v.z = v.w = 0.f;
                if (gm < NN && gk < KTOT)
                    v = *(const float4*)(g_h1 + (long)gm * H1 + gk);
                a4[j] = v;
            }
        }
#pragma unroll
        for (int j = 0; j < 4; j++) {
            int idx = tid + j * 256;                  // [0,1024)
            int n = idx & 63, kk = idx >> 6;
            int gn = n0 + n, gk = k0 + kk;
            float v = 0.f;
            if (gk < KTOT) {
                if (WHICH == 1) {
                    if (gn < 300)
                        v = (gk < F0) ? W[(long)gk * H1 + gn]
                                      : W[(long)F0 * H1 + (long)(gk - F0) * H1 + gn];
                } else {
                    if (gn < 100) v = W[(long)gk * H2 + gn];
                    else if (gn < 200) v = W[(long)H1 * H2 + (long)gk * H2 + (gn - 100)];
                }
            }
            br[j] = v;
        }
    };

    auto STS = [&]() {
        if (WHICH == 1) {
#pragma unroll
            for (int j = 0; j < 4; j++) {
                int idx = tid + j * 256;
                int m = idx >> 3, kk = (idx & 7) * 2;
                float2 v = a2[j];
                uint32_t hx = f2tf32(v.x), hy = f2tf32(v.y);
                As_hi[m * SSTR + kk]     = hx;
                As_hi[m * SSTR + kk + 1] = hy;
                As_lo[m * SSTR + kk]     = f2tf32(v.x - __uint_as_float(hx));
                As_lo[m * SSTR + kk + 1] = f2tf32(v.y - __uint_as_float(hy));
            }
        } else {
#pragma unroll
            for (int j = 0; j < 2; j++) {
                int idx = tid + j * 256;
                int m = idx >> 2, kk = (idx & 3) * 4;
                float4 v = a4[j];
                uint32_t h0 = f2tf32(v.x), h1 = f2tf32(v.y), h2 = f2tf32(v.z), h3 = f2tf32(v.w);
                *(uint4*)&As_hi[m * SSTR + kk] = make_uint4(h0, h1, h2, h3);
                *(uint4*)&As_lo[m * SSTR + kk] = make_uint4(
                    f2tf32(v.x - __uint_as_float(h0)), f2tf32(v.y - __uint_as_float(h1)),
                    f2tf32(v.z - __uint_as_float(h2)), f2tf32(v.w - __uint_as_float(h3)));
            }
        }
#pragma unroll
        for (int j = 0; j < 4; j++) {
            int idx = tid + j * 256;
            int n = idx & 63, kk = idx >> 6;
            uint32_t h = f2tf32(br[j]);
            Bs_hi[n * SSTR + kk] = h;
            Bs_lo[n * SSTR + kk] = f2tf32(br[j] - __uint_as_float(h));
        }
    };

    LDG(0);
    for (int ch = 0; ch < NCH; ch++) {
        STS();
        __syncthreads();
        if (ch + 1 < NCH) LDG((ch + 1) * 16);   // hide gmem latency under mma mainloop

#pragma unroll
        for (int ks = 0; ks < 16; ks += 8) {
            uint32_t ah[2][4], al[2][4];
#pragma unroll
            for (int mt = 0; mt < 2; mt++) {
                int mb = wm * 32 + mt * 16;
                int r0 = (mb + qm) * SSTR + ks + qk;
                int r1 = (mb + qm + 8) * SSTR + ks + qk;
                ah[mt][0] = As_hi[r0];     ah[mt][1] = As_hi[r1];
                ah[mt][2] = As_hi[r0 + 4]; ah[mt][3] = As_hi[r1 + 4];
                al[mt][0] = As_lo[r0];     al[mt][1] = As_lo[r1];
                al[mt][2] = As_lo[r0 + 4]; al[mt][3] = As_lo[r1 + 4];
            }
#pragma unroll
            for (int nt = 0; nt < 4; nt++) {
                int nb = (wn * 32 + nt * 8 + qm) * SSTR + ks + qk;
                uint32_t bh0 = Bs_hi[nb], bh1 = Bs_hi[nb + 4];
                uint32_t bl0 = Bs_lo[nb], bl1 = Bs_lo[nb + 4];
#pragma unroll
                for (int mt = 0; mt < 2; mt++) {
                    mma8(c[mt][nt], ah[mt][0], ah[mt][1], ah[mt][2], ah[mt][3], bh0, bh1);
                    mma8(c[mt][nt], ah[mt][0], ah[mt][1], ah[mt][2], ah[mt][3], bl0, bl1);
                    mma8(c[mt][nt], al[mt][0], al[mt][1], al[mt][2], al[mt][3], bh0, bh1);
                }
            }
        }
        __syncthreads();
    }

    // ---- epilogue ----
#pragma unroll
    for (int mt = 0; mt < 2; mt++) {
#pragma unroll
        for (int nt = 0; nt < 4; nt++) {
            int r0 = m0 + wm * 32 + mt * 16 + qm;
            int col = n0 + wn * 32 + nt * 8 + 2 * qk;
#pragma unroll
            for (int half = 0; half < 2; half++) {
                int r = r0 + half * 8;
                if (r >= NN) continue;
#pragma unroll
                for (int j = 0; j < 2; j++) {
                    int cc = col + j;
                    if (cc >= NCOLS) continue;
                    float v = c[mt][nt][half * 2 + j];
                    if (WHICH == 1) {
                        v = fmaxf(v + bias[cc], 0.f);
                        g_h1[(long)r * H1 + cc] = v;
                    } else {
                        if (cc < 100) v += bias[cc];
                        g_yz2[(long)r * 200 + cc] = v;
                    }
                }
            }
        }
    }
}

// ============================ launch =============================================
extern "C" void kernel_launch(void* const* d_in, const int* in_sizes, int n_in,
                              void* d_out, int out_size) {
    const float* x    = (const float*)d_in[0];
    const int*   ei32 = (const int*)d_in[1];
    const float* W1 = (const float*)d_in[2];
    const float* b1 = (const float*)d_in[3];
    const float* W2 = (const float*)d_in[4];
    const float* b2 = (const float*)d_in[5];
    const float* W3 = (const float*)d_in[6];
    const float* b3 = (const float*)d_in[7];
    float* out = (float*)d_out;

    const int T = 256;
    const int WARP_GRID = (NN * 32 + T - 1) / T;

    k_detect<<<1, 32>>>(ei32);
    k_init<<<NBLK, T>>>();
    k_compact<<<(EE + T - 1) / T, T>>>(ei32);
    k_part<<<NBLK, T>>>();
    k_spart<<<1, 512>>>();
    k_apply<<<NBLK, T>>>();
    k_fill<<<(EE + T - 1) / T, T>>>();

    g_gather1<<<WARP_GRID, T>>>(x);
    mma_gemm<1><<<dim3((H1 + 63) / 64, (NN + 127) / 128), T>>>(x, W1, b1);
    mma_gemm<2><<<dim3((2 * H2 + 63) / 64, (NN + 127) / 128), T>>>(nullptr, W2, b2);
    g_fuse2<<<WARP_GRID, T>>>(W3, b3);
    g_gather3<<<NBLK, T>>>(out);
}